// round 1
// baseline (speedup 1.0000x reference)
#include <cuda_runtime.h>
#include <cstdint>

// ----------------------------------------------------------------------------
// MambaBlock: out = (silu(depthwise_conv3(v)) * u) @ Wo^T + bo
//   where [u|v] = x @ Wi^T + bi
// Shapes: x[4,4096,1024]  Wi[2048,1024]  bi[2048]  Wc[1024,1,3]  bc[1024]
//         Wo[1024,1024]   bo[1024]       out[4,4096,1024]  (all fp32)
// Round 1: correct fp32 baseline. SGEMM-NT 128x128x16, 8x8 per thread.
// ----------------------------------------------------------------------------

#define MROWS   16384          // 4 * 4096
#define DDIM    1024
#define LSEQ    4096

#define BM 128
#define BN 128
#define BK 16
#define TM 8
#define TN 8
#define NTHREADS 256

// Scratch (allocation-free rule: __device__ globals)
__device__ float g_uv[(size_t)MROWS * 2 * DDIM];   // [M, 2048]: cols [0,1024)=u, [1024,2048)=v
__device__ float g_y [(size_t)MROWS * DDIM];       // gated conv output

// C[M,N] = A[M,K] * B[N,K]^T + bias[N]
// A row-major [M,K], B row-major [N,K]. M,N,K all multiples of tile sizes here.
template <int N, int K>
__global__ __launch_bounds__(NTHREADS)
void sgemm_nt(const float* __restrict__ A,
              const float* __restrict__ B,
              const float* __restrict__ bias,
              float* __restrict__ C)
{
    __shared__ float As[BK][BM];
    __shared__ float Bs[BK][BN];

    const int tid  = threadIdx.x;
    const int row0 = blockIdx.y * BM;
    const int col0 = blockIdx.x * BN;

    const int tx = tid & 15;    // 16 thread cols * TN(8) = 128
    const int ty = tid >> 4;    // 16 thread rows * TM(8) = 128

    float acc[TM][TN];
#pragma unroll
    for (int i = 0; i < TM; i++)
#pragma unroll
        for (int j = 0; j < TN; j++) acc[i][j] = 0.f;

    const float* Ablk = A + (size_t)row0 * K;
    const float* Bblk = B + (size_t)col0 * K;

    for (int kt = 0; kt < K; kt += BK) {
        // Load 128x16 A tile and 128x16 B tile. 512 float4 each, 2 per thread.
#pragma unroll
        for (int rep = 0; rep < 2; rep++) {
            int i  = tid + rep * NTHREADS;  // float4 id in [0,512)
            int r  = i >> 2;                // tile row 0..127
            int c4 = i & 3;                 // float4 col 0..3
            float4 va = *(const float4*)(Ablk + (size_t)r * K + kt + c4 * 4);
            As[c4 * 4 + 0][r] = va.x;
            As[c4 * 4 + 1][r] = va.y;
            As[c4 * 4 + 2][r] = va.z;
            As[c4 * 4 + 3][r] = va.w;
            float4 vb = *(const float4*)(Bblk + (size_t)r * K + kt + c4 * 4);
            Bs[c4 * 4 + 0][r] = vb.x;
            Bs[c4 * 4 + 1][r] = vb.y;
            Bs[c4 * 4 + 2][r] = vb.z;
            Bs[c4 * 4 + 3][r] = vb.w;
        }
        __syncthreads();

#pragma unroll
        for (int kk = 0; kk < BK; kk++) {
            float ra[TM], rb[TN];
#pragma unroll
            for (int i = 0; i < TM; i++) ra[i] = As[kk][ty * TM + i];
#pragma unroll
            for (int j = 0; j < TN; j++) rb[j] = Bs[kk][tx * TN + j];
#pragma unroll
            for (int i = 0; i < TM; i++)
#pragma unroll
                for (int j = 0; j < TN; j++)
                    acc[i][j] = fmaf(ra[i], rb[j], acc[i][j]);
        }
        __syncthreads();
    }

    // Epilogue: add bias, vectorized stores
#pragma unroll
    for (int i = 0; i < TM; i++) {
        int r = row0 + ty * TM + i;
#pragma unroll
        for (int j = 0; j < TN; j += 4) {
            int c = col0 + tx * TN + j;
            float4 o;
            o.x = acc[i][j + 0] + bias[c + 0];
            o.y = acc[i][j + 1] + bias[c + 1];
            o.z = acc[i][j + 2] + bias[c + 2];
            o.w = acc[i][j + 3] + bias[c + 3];
            *(float4*)(C + (size_t)r * N + c) = o;
        }
    }
}

// y[m,d] = silu( v[l-1,d]*Wc[d,0] + v[l,d]*Wc[d,1] + v[l+1,d]*Wc[d,2] + bc[d] ) * u[m,d]
// with zero padding at sequence (per-batch) boundaries. One float4 of d per thread.
__global__ __launch_bounds__(256)
void conv_gate_kernel(const float* __restrict__ Wc, const float* __restrict__ bc)
{
    int idx = blockIdx.x * blockDim.x + threadIdx.x;   // [0, MROWS * 256)
    int m  = idx >> 8;            // row
    int d  = (idx & 255) << 2;    // feature, float4 aligned
    int l  = m & (LSEQ - 1);      // position within batch

    const float* urow = g_uv + (size_t)m * (2 * DDIM);
    const float* vrow = urow + DDIM;

    float4 vc = *(const float4*)(vrow + d);
    float4 vp = make_float4(0.f, 0.f, 0.f, 0.f);
    float4 vn = make_float4(0.f, 0.f, 0.f, 0.f);
    if (l > 0)        vp = *(const float4*)(vrow - 2 * DDIM + d);
    if (l < LSEQ - 1) vn = *(const float4*)(vrow + 2 * DDIM + d);
    float4 uu = *(const float4*)(urow + d);

    float p[4] = {vp.x, vp.y, vp.z, vp.w};
    float c[4] = {vc.x, vc.y, vc.z, vc.w};
    float n[4] = {vn.x, vn.y, vn.z, vn.w};
    float u[4] = {uu.x, uu.y, uu.z, uu.w};
    float o[4];

#pragma unroll
    for (int j = 0; j < 4; j++) {
        int dd = d + j;
        float t = fmaf(p[j], Wc[dd * 3 + 0],
                  fmaf(c[j], Wc[dd * 3 + 1],
                  fmaf(n[j], Wc[dd * 3 + 2], bc[dd])));
        float s = 1.f / (1.f + __expf(-t));
        o[j] = t * s * u[j];
    }
    float4 ov = make_float4(o[0], o[1], o[2], o[3]);
    *(float4*)(g_y + (size_t)m * DDIM + d) = ov;
}

extern "C" void kernel_launch(void* const* d_in, const int* in_sizes, int n_in,
                              void* d_out, int out_size)
{
    const float* x  = (const float*)d_in[0];
    const float* Wi = (const float*)d_in[1];
    const float* bi = (const float*)d_in[2];
    const float* Wc = (const float*)d_in[3];
    const float* bc = (const float*)d_in[4];
    const float* Wo = (const float*)d_in[5];
    const float* bo = (const float*)d_in[6];
    float* out = (float*)d_out;

    float *uv_ptr, *y_ptr;
    cudaGetSymbolAddress((void**)&uv_ptr, g_uv);
    cudaGetSymbolAddress((void**)&y_ptr,  g_y);

    // GEMM1: g_uv[M,2048] = x[M,1024] * Wi[2048,1024]^T + bi
    {
        dim3 grid(2 * DDIM / BN, MROWS / BM);   // (16, 128)
        sgemm_nt<2 * DDIM, DDIM><<<grid, NTHREADS>>>(x, Wi, bi, uv_ptr);
    }

    // conv + silu gate: g_y[M,1024]
    {
        int total = MROWS * (DDIM / 4);
        conv_gate_kernel<<<total / 256, 256>>>(Wc, bc);
    }

    // GEMM2: out[M,1024] = g_y[M,1024] * Wo[1024,1024]^T + bo
    {
        dim3 grid(DDIM / BN, MROWS / BM);       // (8, 128)
        sgemm_nt<DDIM, DDIM><<<grid, NTHREADS>>>(y_ptr, Wo, bo, out);
    }
}

// round 3
// speedup vs baseline: 2.6179x; 2.6179x over previous
#include <cuda_runtime.h>
#include <cuda_bf16.h>
#include <cstdint>

// ============================================================================
// MambaBlock via mma.sync (HMMA) bf16 3-product split, fp32 accumulate.
//   uv = x@Wi^T+bi ; y = silu(dwconv3(v))*u ; out = y@Wo^T+bo
// PTX target is compute_103 (no 'a'): tcgen05 unavailable, mma.sync is.
// ============================================================================

#define MROWS 16384
#define DDIM  1024
#define LSEQ  4096

#define BM 128
#define BN 128
#define BK 32
#define SP 40                    // SMEM row stride in bf16 elems (32 + 8 pad)
#define NTH 256

#define A_HI 0
#define A_LO (BM * SP * 2)       // 10240
#define B_HI (2 * BM * SP * 2)   // 20480
#define B_LO (3 * BM * SP * 2)   // 30720
#define STAGE_BYTES (4 * BM * SP * 2)   // 40960
#define SMEMSZ (2 * STAGE_BYTES)        // 81920

__device__ float g_uv[(size_t)MROWS * 2 * DDIM];   // [M,2048]: u | v
__device__ float g_y [(size_t)MROWS * DDIM];

__device__ __forceinline__ void mma_bf16(float* c, const uint32_t* a,
                                         uint32_t b0, uint32_t b1) {
    asm volatile(
        "mma.sync.aligned.m16n8k16.row.col.f32.bf16.bf16.f32 "
        "{%0,%1,%2,%3}, {%4,%5,%6,%7}, {%8,%9}, {%0,%1,%2,%3};"
        : "+f"(c[0]), "+f"(c[1]), "+f"(c[2]), "+f"(c[3])
        : "r"(a[0]), "r"(a[1]), "r"(a[2]), "r"(a[3]), "r"(b0), "r"(b1));
}

// fp32x4 -> bf16 hi (2 words) + bf16 lo residual (2 words)
__device__ __forceinline__ void cvt_hilo(float4 v, uint32_t& h0, uint32_t& h1,
                                         uint32_t& l0, uint32_t& l1) {
    __nv_bfloat162 H0 = __floats2bfloat162_rn(v.x, v.y);
    __nv_bfloat162 H1 = __floats2bfloat162_rn(v.z, v.w);
    float r0 = v.x - __bfloat162float(H0.x);
    float r1 = v.y - __bfloat162float(H0.y);
    float r2 = v.z - __bfloat162float(H1.x);
    float r3 = v.w - __bfloat162float(H1.y);
    __nv_bfloat162 L0 = __floats2bfloat162_rn(r0, r1);
    __nv_bfloat162 L1 = __floats2bfloat162_rn(r2, r3);
    h0 = *reinterpret_cast<uint32_t*>(&H0);
    h1 = *reinterpret_cast<uint32_t*>(&H1);
    l0 = *reinterpret_cast<uint32_t*>(&L0);
    l1 = *reinterpret_cast<uint32_t*>(&L1);
}

// C[M,N] = A[M,K] @ B[N,K]^T + bias,  fp32 in/out, bf16x3 internally.
template <int N, int K>
__global__ __launch_bounds__(NTH, 1)
void gemm_mma(const float* __restrict__ A, const float* __restrict__ B,
              const float* __restrict__ bias, float* __restrict__ C) {
    extern __shared__ __align__(16) char sm[];
    const int tid  = threadIdx.x;
    const int lane = tid & 31;
    const int wid  = tid >> 5;
    const int wm   = wid & 3;        // 4 warp-rows * 32 = 128 M
    const int wn   = wid >> 2;       // 2 warp-cols * 64 = 128 N
    const int qr   = lane >> 2;      // 0..7
    const int qc   = (lane & 3) * 2; // 0,2,4,6
    const int row0 = blockIdx.y * BM;
    const int col0 = blockIdx.x * BN;

    const int lr = tid >> 3;         // loader row base (0..31), + rep*32
    const int lc = tid & 7;          // loader float4-col (0..7)

    float acc[2][8][4];
#pragma unroll
    for (int i = 0; i < 2; i++)
#pragma unroll
        for (int j = 0; j < 8; j++)
#pragma unroll
            for (int k = 0; k < 4; k++) acc[i][j][k] = 0.f;

    const float* Ab = A + (size_t)row0 * K;
    const float* Bb = B + (size_t)col0 * K;

    // ---- prologue: chunk 0 -> stage 0 ----
    {
        char* st = sm;
#pragma unroll
        for (int rep = 0; rep < 4; rep++) {
            int r = lr + rep * 32;
            float4 va = *(const float4*)(Ab + (size_t)r * K + lc * 4);
            float4 vb = *(const float4*)(Bb + (size_t)r * K + lc * 4);
            uint32_t h0, h1, l0, l1;
            int off = r * (SP * 2) + lc * 8;
            cvt_hilo(va, h0, h1, l0, l1);
            *(uint2*)(st + A_HI + off) = make_uint2(h0, h1);
            *(uint2*)(st + A_LO + off) = make_uint2(l0, l1);
            cvt_hilo(vb, h0, h1, l0, l1);
            *(uint2*)(st + B_HI + off) = make_uint2(h0, h1);
            *(uint2*)(st + B_LO + off) = make_uint2(l0, l1);
        }
    }

    constexpr int NCH = K / BK;
    for (int ck = 0; ck < NCH; ck++) {
        __syncthreads();
        const char* st = sm + (size_t)(ck & 1) * STAGE_BYTES;
        char* stn      = sm + (size_t)((ck + 1) & 1) * STAGE_BYTES;

        // prefetch next chunk into registers (hides DRAM/L2 latency)
        float4 pa[4], pb[4];
        const bool pf = (ck + 1 < NCH);
        if (pf) {
            const int kt = (ck + 1) * BK;
#pragma unroll
            for (int rep = 0; rep < 4; rep++) {
                int r = lr + rep * 32;
                pa[rep] = *(const float4*)(Ab + (size_t)r * K + kt + lc * 4);
                pb[rep] = *(const float4*)(Bb + (size_t)r * K + kt + lc * 4);
            }
        }

        // compute on stage st
#pragma unroll
        for (int kb = 0; kb < BK; kb += 16) {
            uint32_t ah[2][4], al[2][4];
#pragma unroll
            for (int mt = 0; mt < 2; mt++) {
                const char* ba = st + ((wm * 32 + mt * 16 + qr) * SP + kb + qc) * 2;
                ah[mt][0] = *(const uint32_t*)(ba + A_HI);
                ah[mt][1] = *(const uint32_t*)(ba + A_HI + 8 * SP * 2);
                ah[mt][2] = *(const uint32_t*)(ba + A_HI + 16);
                ah[mt][3] = *(const uint32_t*)(ba + A_HI + 8 * SP * 2 + 16);
                al[mt][0] = *(const uint32_t*)(ba + A_LO);
                al[mt][1] = *(const uint32_t*)(ba + A_LO + 8 * SP * 2);
                al[mt][2] = *(const uint32_t*)(ba + A_LO + 16);
                al[mt][3] = *(const uint32_t*)(ba + A_LO + 8 * SP * 2 + 16);
            }
#pragma unroll
            for (int nt = 0; nt < 8; nt++) {
                const char* bb = st + ((wn * 64 + nt * 8 + qr) * SP + kb + qc) * 2;
                uint32_t bh0 = *(const uint32_t*)(bb + B_HI);
                uint32_t bh1 = *(const uint32_t*)(bb + B_HI + 16);
                uint32_t bl0 = *(const uint32_t*)(bb + B_LO);
                uint32_t bl1 = *(const uint32_t*)(bb + B_LO + 16);
#pragma unroll
                for (int mt = 0; mt < 2; mt++) {
                    mma_bf16(acc[mt][nt], ah[mt], bh0, bh1);  // hi*hi
                    mma_bf16(acc[mt][nt], al[mt], bh0, bh1);  // lo*hi
                    mma_bf16(acc[mt][nt], ah[mt], bl0, bl1);  // hi*lo
                }
            }
        }

        // store prefetched chunk into the other stage
        if (pf) {
#pragma unroll
            for (int rep = 0; rep < 4; rep++) {
                int r = lr + rep * 32;
                int off = r * (SP * 2) + lc * 8;
                uint32_t h0, h1, l0, l1;
                cvt_hilo(pa[rep], h0, h1, l0, l1);
                *(uint2*)(stn + A_HI + off) = make_uint2(h0, h1);
                *(uint2*)(stn + A_LO + off) = make_uint2(l0, l1);
                cvt_hilo(pb[rep], h0, h1, l0, l1);
                *(uint2*)(stn + B_HI + off) = make_uint2(h0, h1);
                *(uint2*)(stn + B_LO + off) = make_uint2(l0, l1);
            }
        }
    }

    // ---- epilogue: bias + store ----
#pragma unroll
    for (int mt = 0; mt < 2; mt++) {
        int row = row0 + wm * 32 + mt * 16 + qr;
#pragma unroll
        for (int nt = 0; nt < 8; nt++) {
            int col = col0 + wn * 64 + nt * 8 + qc;
            float b0 = __ldg(&bias[col]);
            float b1 = __ldg(&bias[col + 1]);
            float2 o0 = make_float2(acc[mt][nt][0] + b0, acc[mt][nt][1] + b1);
            float2 o1 = make_float2(acc[mt][nt][2] + b0, acc[mt][nt][3] + b1);
            *(float2*)(C + (size_t)row * N + col) = o0;
            *(float2*)(C + (size_t)(row + 8) * N + col) = o1;
        }
    }
}

// ---------------------------------------------------------------------------
// depthwise conv3 + silu gate (memory-bound)
// ---------------------------------------------------------------------------
__global__ __launch_bounds__(256)
void conv_gate_kernel(const float* __restrict__ Wc, const float* __restrict__ bc) {
    int idx = blockIdx.x * blockDim.x + threadIdx.x;
    int m = idx >> 8;
    int d = (idx & 255) << 2;
    int l = m & (LSEQ - 1);

    const float* urow = g_uv + (size_t)m * (2 * DDIM);
    const float* vrow = urow + DDIM;

    float4 vc = *(const float4*)(vrow + d);
    float4 vp = make_float4(0.f, 0.f, 0.f, 0.f);
    float4 vn = make_float4(0.f, 0.f, 0.f, 0.f);
    if (l > 0)        vp = *(const float4*)(vrow - 2 * DDIM + d);
    if (l < LSEQ - 1) vn = *(const float4*)(vrow + 2 * DDIM + d);
    float4 uu = *(const float4*)(urow + d);

    float p[4] = {vp.x, vp.y, vp.z, vp.w};
    float c[4] = {vc.x, vc.y, vc.z, vc.w};
    float n[4] = {vn.x, vn.y, vn.z, vn.w};
    float u[4] = {uu.x, uu.y, uu.z, uu.w};
    float o[4];
#pragma unroll
    for (int j = 0; j < 4; j++) {
        int dd = d + j;
        float t = fmaf(p[j], Wc[dd * 3 + 0],
                  fmaf(c[j], Wc[dd * 3 + 1],
                  fmaf(n[j], Wc[dd * 3 + 2], bc[dd])));
        float s = 1.f / (1.f + __expf(-t));
        o[j] = t * s * u[j];
    }
    *(float4*)(g_y + (size_t)m * DDIM + d) = make_float4(o[0], o[1], o[2], o[3]);
}

// ---------------------------------------------------------------------------
extern "C" void kernel_launch(void* const* d_in, const int* in_sizes, int n_in,
                              void* d_out, int out_size) {
    const float* x  = (const float*)d_in[0];
    const float* Wi = (const float*)d_in[1];
    const float* bi = (const float*)d_in[2];
    const float* Wc = (const float*)d_in[3];
    const float* bc = (const float*)d_in[4];
    const float* Wo = (const float*)d_in[5];
    const float* bo = (const float*)d_in[6];
    float* out = (float*)d_out;

    float *uv_ptr, *y_ptr;
    cudaGetSymbolAddress((void**)&uv_ptr, g_uv);
    cudaGetSymbolAddress((void**)&y_ptr,  g_y);

    cudaFuncSetAttribute(gemm_mma<2 * DDIM, DDIM>,
                         cudaFuncAttributeMaxDynamicSharedMemorySize, SMEMSZ);
    cudaFuncSetAttribute(gemm_mma<DDIM, DDIM>,
                         cudaFuncAttributeMaxDynamicSharedMemorySize, SMEMSZ);

    {   // GEMM1: uv[M,2048] = x @ Wi^T + bi
        dim3 grid(2 * DDIM / BN, MROWS / BM);   // (16, 128)
        gemm_mma<2 * DDIM, DDIM><<<grid, NTH, SMEMSZ>>>(x, Wi, bi, uv_ptr);
    }
    {   // conv + silu gate
        int total = MROWS * (DDIM / 4);
        conv_gate_kernel<<<total / 256, 256>>>(Wc, bc);
    }
    {   // GEMM2: out[M,1024] = y @ Wo^T + bo
        dim3 grid(DDIM / BN, MROWS / BM);       // (8, 128)
        gemm_mma<DDIM, DDIM><<<grid, NTH, SMEMSZ>>>(y_ptr, Wo, bo, out);
    }
}

// round 4
// speedup vs baseline: 2.8299x; 1.0810x over previous
#include <cuda_runtime.h>
#include <cuda_bf16.h>
#include <cstdint>

// ============================================================================
// MambaBlock via mma.sync (HMMA) bf16 3-product split, fp32 accumulate.
// R4: ldmatrix fragment loads (conflict-free) to unstarve the tensor pipe.
// ============================================================================

#define MROWS 16384
#define DDIM  1024
#define LSEQ  4096

#define BM 128
#define BN 128
#define BK 32
#define SP 40                    // SMEM row stride in bf16 elems (32 + 8 pad)
#define NTH 256

#define A_HI 0
#define A_LO (BM * SP * 2)       // 10240
#define B_HI (2 * BM * SP * 2)   // 20480
#define B_LO (3 * BM * SP * 2)   // 30720
#define STAGE_BYTES (4 * BM * SP * 2)   // 40960
#define SMEMSZ (2 * STAGE_BYTES)        // 81920

__device__ float g_uv[(size_t)MROWS * 2 * DDIM];   // [M,2048]: u | v
__device__ float g_y [(size_t)MROWS * DDIM];

__device__ __forceinline__ void mma_bf16(float* c, const uint32_t* a,
                                         uint32_t b0, uint32_t b1) {
    asm volatile(
        "mma.sync.aligned.m16n8k16.row.col.f32.bf16.bf16.f32 "
        "{%0,%1,%2,%3}, {%4,%5,%6,%7}, {%8,%9}, {%0,%1,%2,%3};"
        : "+f"(c[0]), "+f"(c[1]), "+f"(c[2]), "+f"(c[3])
        : "r"(a[0]), "r"(a[1]), "r"(a[2]), "r"(a[3]), "r"(b0), "r"(b1));
}

#define LDSM4(r0, r1, r2, r3, addr)                                        \
    asm volatile("ldmatrix.sync.aligned.m8n8.x4.shared.b16 {%0,%1,%2,%3}, [%4];" \
                 : "=r"(r0), "=r"(r1), "=r"(r2), "=r"(r3) : "r"(addr))

// fp32x4 -> bf16 hi (2 words) + bf16 lo residual (2 words)
__device__ __forceinline__ void cvt_hilo(float4 v, uint32_t& h0, uint32_t& h1,
                                         uint32_t& l0, uint32_t& l1) {
    __nv_bfloat162 H0 = __floats2bfloat162_rn(v.x, v.y);
    __nv_bfloat162 H1 = __floats2bfloat162_rn(v.z, v.w);
    float r0 = v.x - __bfloat162float(H0.x);
    float r1 = v.y - __bfloat162float(H0.y);
    float r2 = v.z - __bfloat162float(H1.x);
    float r3 = v.w - __bfloat162float(H1.y);
    __nv_bfloat162 L0 = __floats2bfloat162_rn(r0, r1);
    __nv_bfloat162 L1 = __floats2bfloat162_rn(r2, r3);
    h0 = *reinterpret_cast<uint32_t*>(&H0);
    h1 = *reinterpret_cast<uint32_t*>(&H1);
    l0 = *reinterpret_cast<uint32_t*>(&L0);
    l1 = *reinterpret_cast<uint32_t*>(&L1);
}

// C[M,N] = A[M,K] @ B[N,K]^T + bias,  fp32 in/out, bf16x3 internally.
template <int N, int K>
__global__ __launch_bounds__(NTH, 1)
void gemm_mma(const float* __restrict__ A, const float* __restrict__ B,
              const float* __restrict__ bias, float* __restrict__ C) {
    extern __shared__ __align__(16) char sm[];
    const uint32_t smb = (uint32_t)__cvta_generic_to_shared(sm);
    const int tid  = threadIdx.x;
    const int lane = tid & 31;
    const int wid  = tid >> 5;
    const int wm   = wid & 3;        // 4 warp-rows * 32 = 128 M
    const int wn   = wid >> 2;       // 2 warp-cols * 64 = 128 N
    const int qr   = lane >> 2;
    const int qc   = (lane & 3) * 2;
    const int row0 = blockIdx.y * BM;
    const int col0 = blockIdx.x * BN;

    const int lr = tid >> 3;         // loader row base (0..31), + rep*32
    const int lc = tid & 7;          // loader float4-col (0..7)

    // per-lane ldmatrix base offsets (within a stage)
    const int m8 = lane >> 3;        // submatrix id 0..3
    const int rr = lane & 7;
    const uint32_t aLane = (uint32_t)(((wm * 32 + (m8 & 1) * 8 + rr) * SP + (m8 >> 1) * 8) * 2);
    const uint32_t bLane = (uint32_t)(((wn * 64 + (m8 >> 1) * 8 + rr) * SP + (m8 & 1) * 8) * 2);

    float acc[2][8][4];
#pragma unroll
    for (int i = 0; i < 2; i++)
#pragma unroll
        for (int j = 0; j < 8; j++)
#pragma unroll
            for (int k = 0; k < 4; k++) acc[i][j][k] = 0.f;

    const float* Ab = A + (size_t)row0 * K;
    const float* Bb = B + (size_t)col0 * K;

    // ---- prologue: chunk 0 -> stage 0 ----
    {
        char* st = sm;
#pragma unroll
        for (int rep = 0; rep < 4; rep++) {
            int r = lr + rep * 32;
            float4 va = *(const float4*)(Ab + (size_t)r * K + lc * 4);
            float4 vb = *(const float4*)(Bb + (size_t)r * K + lc * 4);
            uint32_t h0, h1, l0, l1;
            int off = r * (SP * 2) + lc * 8;
            cvt_hilo(va, h0, h1, l0, l1);
            *(uint2*)(st + A_HI + off) = make_uint2(h0, h1);
            *(uint2*)(st + A_LO + off) = make_uint2(l0, l1);
            cvt_hilo(vb, h0, h1, l0, l1);
            *(uint2*)(st + B_HI + off) = make_uint2(h0, h1);
            *(uint2*)(st + B_LO + off) = make_uint2(l0, l1);
        }
    }

    constexpr int NCH = K / BK;
    for (int ck = 0; ck < NCH; ck++) {
        __syncthreads();
        const uint32_t sto = smb + (uint32_t)((ck & 1) * STAGE_BYTES);
        char* stn = sm + (size_t)((ck + 1) & 1) * STAGE_BYTES;

        // prefetch next chunk into registers
        float4 pa[4], pb[4];
        const bool pf = (ck + 1 < NCH);
        if (pf) {
            const int kt = (ck + 1) * BK;
#pragma unroll
            for (int rep = 0; rep < 4; rep++) {
                int r = lr + rep * 32;
                pa[rep] = *(const float4*)(Ab + (size_t)r * K + kt + lc * 4);
                pb[rep] = *(const float4*)(Bb + (size_t)r * K + kt + lc * 4);
            }
        }

        // compute on current stage
#pragma unroll
        for (int kb = 0; kb < BK; kb += 16) {
            uint32_t ah[2][4], al[2][4];
#pragma unroll
            for (int mt = 0; mt < 2; mt++) {
                uint32_t ao = sto + aLane + (uint32_t)((mt * 16 * SP + kb) * 2);
                LDSM4(ah[mt][0], ah[mt][1], ah[mt][2], ah[mt][3], ao + A_HI);
                LDSM4(al[mt][0], al[mt][1], al[mt][2], al[mt][3], ao + A_LO);
            }
#pragma unroll
            for (int ntp = 0; ntp < 4; ntp++) {
                uint32_t bo = sto + bLane + (uint32_t)((ntp * 16 * SP + kb) * 2);
                uint32_t bh0, bh1, bh2, bh3, bl0, bl1, bl2, bl3;
                LDSM4(bh0, bh1, bh2, bh3, bo + B_HI);
                LDSM4(bl0, bl1, bl2, bl3, bo + B_LO);
#pragma unroll
                for (int mt = 0; mt < 2; mt++) {
                    float* c0 = acc[mt][2 * ntp];
                    float* c1 = acc[mt][2 * ntp + 1];
                    mma_bf16(c0, ah[mt], bh0, bh1);   // hi*hi
                    mma_bf16(c1, ah[mt], bh2, bh3);
                    mma_bf16(c0, al[mt], bh0, bh1);   // lo*hi
                    mma_bf16(c1, al[mt], bh2, bh3);
                    mma_bf16(c0, ah[mt], bl0, bl1);   // hi*lo
                    mma_bf16(c1, ah[mt], bl2, bl3);
                }
            }
        }

        // store prefetched chunk into the other stage
        if (pf) {
#pragma unroll
            for (int rep = 0; rep < 4; rep++) {
                int r = lr + rep * 32;
                int off = r * (SP * 2) + lc * 8;
                uint32_t h0, h1, l0, l1;
                cvt_hilo(pa[rep], h0, h1, l0, l1);
                *(uint2*)(stn + A_HI + off) = make_uint2(h0, h1);
                *(uint2*)(stn + A_LO + off) = make_uint2(l0, l1);
                cvt_hilo(pb[rep], h0, h1, l0, l1);
                *(uint2*)(stn + B_HI + off) = make_uint2(h0, h1);
                *(uint2*)(stn + B_LO + off) = make_uint2(l0, l1);
            }
        }
    }

    // ---- epilogue: bias + store ----
#pragma unroll
    for (int mt = 0; mt < 2; mt++) {
        int row = row0 + wm * 32 + mt * 16 + qr;
#pragma unroll
        for (int nt = 0; nt < 8; nt++) {
            int col = col0 + wn * 64 + nt * 8 + qc;
            float b0 = __ldg(&bias[col]);
            float b1 = __ldg(&bias[col + 1]);
            float2 o0 = make_float2(acc[mt][nt][0] + b0, acc[mt][nt][1] + b1);
            float2 o1 = make_float2(acc[mt][nt][2] + b0, acc[mt][nt][3] + b1);
            *(float2*)(C + (size_t)row * N + col) = o0;
            *(float2*)(C + (size_t)(row + 8) * N + col) = o1;
        }
    }
}

// ---------------------------------------------------------------------------
// depthwise conv3 + silu gate (memory-bound)
// ---------------------------------------------------------------------------
__global__ __launch_bounds__(256)
void conv_gate_kernel(const float* __restrict__ Wc, const float* __restrict__ bc) {
    int idx = blockIdx.x * blockDim.x + threadIdx.x;
    int m = idx >> 8;
    int d = (idx & 255) << 2;
    int l = m & (LSEQ - 1);

    const float* urow = g_uv + (size_t)m * (2 * DDIM);
    const float* vrow = urow + DDIM;

    float4 vc = *(const float4*)(vrow + d);
    float4 vp = make_float4(0.f, 0.f, 0.f, 0.f);
    float4 vn = make_float4(0.f, 0.f, 0.f, 0.f);
    if (l > 0)        vp = *(const float4*)(vrow - 2 * DDIM + d);
    if (l < LSEQ - 1) vn = *(const float4*)(vrow + 2 * DDIM + d);
    float4 uu = *(const float4*)(urow + d);

    float p[4] = {vp.x, vp.y, vp.z, vp.w};
    float c[4] = {vc.x, vc.y, vc.z, vc.w};
    float n[4] = {vn.x, vn.y, vn.z, vn.w};
    float u[4] = {uu.x, uu.y, uu.z, uu.w};
    float o[4];
#pragma unroll
    for (int j = 0; j < 4; j++) {
        int dd = d + j;
        float t = fmaf(p[j], Wc[dd * 3 + 0],
                  fmaf(c[j], Wc[dd * 3 + 1],
                  fmaf(n[j], Wc[dd * 3 + 2], bc[dd])));
        float s = 1.f / (1.f + __expf(-t));
        o[j] = t * s * u[j];
    }
    *(float4*)(g_y + (size_t)m * DDIM + d) = make_float4(o[0], o[1], o[2], o[3]);
}

// ---------------------------------------------------------------------------
extern "C" void kernel_launch(void* const* d_in, const int* in_sizes, int n_in,
                              void* d_out, int out_size) {
    const float* x  = (const float*)d_in[0];
    const float* Wi = (const float*)d_in[1];
    const float* bi = (const float*)d_in[2];
    const float* Wc = (const float*)d_in[3];
    const float* bc = (const float*)d_in[4];
    const float* Wo = (const float*)d_in[5];
    const float* bo = (const float*)d_in[6];
    float* out = (float*)d_out;

    float *uv_ptr, *y_ptr;
    cudaGetSymbolAddress((void**)&uv_ptr, g_uv);
    cudaGetSymbolAddress((void**)&y_ptr,  g_y);

    cudaFuncSetAttribute(gemm_mma<2 * DDIM, DDIM>,
                         cudaFuncAttributeMaxDynamicSharedMemorySize, SMEMSZ);
    cudaFuncSetAttribute(gemm_mma<DDIM, DDIM>,
                         cudaFuncAttributeMaxDynamicSharedMemorySize, SMEMSZ);

    {   // GEMM1: uv[M,2048] = x @ Wi^T + bi
        dim3 grid(2 * DDIM / BN, MROWS / BM);   // (16, 128)
        gemm_mma<2 * DDIM, DDIM><<<grid, NTH, SMEMSZ>>>(x, Wi, bi, uv_ptr);
    }
    {   // conv + silu gate
        int total = MROWS * (DDIM / 4);
        conv_gate_kernel<<<total / 256, 256>>>(Wc, bc);
    }
    {   // GEMM2: out[M,1024] = y @ Wo^T + bo
        dim3 grid(DDIM / BN, MROWS / BM);       // (8, 128)
        gemm_mma<DDIM, DDIM><<<grid, NTH, SMEMSZ>>>(y_ptr, Wo, bo, out);
    }
}